// round 17
// baseline (speedup 1.0000x reference)
#include <cuda_runtime.h>
#include <cuda_fp16.h>
#include <math.h>
#include <stdint.h>

#define BB 8
#define SS 2048
#define DD 512
#define MTOT (BB*SS)

__device__ __half g_xh[MTOT*DD];
__device__ __half g_Wth[3][DD*DD];
__device__ float  g_bias[3*DD];
__device__ __half g_QKV[3][MTOT*DD];
__device__ __half g_P[(long long)BB*SS*SS];      // exp(scores), fp16
__device__ float  g_rowsum[MTOT];

__device__ __forceinline__ uint32_t smem_u32(const void* p){
    uint32_t a;
    asm("{ .reg .u64 t; cvta.to.shared.u64 t, %1; cvt.u32.u64 %0, t; }" : "=r"(a) : "l"(p));
    return a;
}
__device__ __forceinline__ void cpa16(uint32_t dst, const void* src){
    asm volatile("cp.async.cg.shared.global [%0], [%1], 16;" :: "r"(dst), "l"(src));
}
__device__ __forceinline__ void cpa_commit(){ asm volatile("cp.async.commit_group;"); }
template<int N> __device__ __forceinline__ void cpa_wait(){
    asm volatile("cp.async.wait_group %0;" :: "n"(N));
}
__device__ __forceinline__ void ldm_x4(uint32_t* r, uint32_t addr){
    asm volatile("ldmatrix.sync.aligned.m8n8.x4.shared.b16 {%0,%1,%2,%3}, [%4];"
        : "=r"(r[0]), "=r"(r[1]), "=r"(r[2]), "=r"(r[3]) : "r"(addr));
}
__device__ __forceinline__ void ldm_x4_t(uint32_t* r, uint32_t addr){
    asm volatile("ldmatrix.sync.aligned.m8n8.x4.trans.shared.b16 {%0,%1,%2,%3}, [%4];"
        : "=r"(r[0]), "=r"(r[1]), "=r"(r[2]), "=r"(r[3]) : "r"(addr));
}
__device__ __forceinline__ void mma16816(float* d, const uint32_t* a, uint32_t b0, uint32_t b1){
    asm volatile("mma.sync.aligned.m16n8k16.row.col.f32.f16.f16.f32 "
        "{%0,%1,%2,%3},{%4,%5,%6,%7},{%8,%9},{%0,%1,%2,%3};"
        : "+f"(d[0]), "+f"(d[1]), "+f"(d[2]), "+f"(d[3])
        : "r"(a[0]), "r"(a[1]), "r"(a[2]), "r"(a[3]), "r"(b0), "r"(b1));
}
__device__ __forceinline__ float ex2(float x){
    float r;
    asm("ex2.approx.ftz.f32 %0, %1;" : "=f"(r) : "f"(x));
    return r;
}
#define L2E 1.44269504f

#define PITCH   80
#define MATB    (128*PITCH)     // A tile: 128 rows x 80B = 10240
#define BPITCH  272
#define BMATB   (32*BPITCH)     // BT B tile: 32 k-rows x 272B = 8704

// 256 threads, 8 warps of 64x32, CTA tile 128x128, K-chunk 32, 3-stage, single sync.
// C = A * op(B), plain fp16 operands.
//   BT=0: B stored [N,K] row-major (ld = K), ldmatrix non-trans
//   BT=1: B stored [K,N] row-major (ld = N), ldmatrix.trans    (V directly!)
// EPI 2: Ch = fp16(D + bias[z])
// EPI 4: Ch = fp16(ex2(alpha*D)); per-row sum of stored values atomicAdd'ed to rowsum
// EPI 5: Cf = D / rowsum[z*SS + row]   (fp32 out)
template<int EPI, int BT>
__global__ void __launch_bounds__(256, 2)
gemm_mma(const __half* __restrict__ Ah, const __half* __restrict__ Bh,
         const float* __restrict__ bias,
         __half* __restrict__ Ch, float* __restrict__ Cf, float* __restrict__ rowsum,
         int N, int K, float alpha,
         long long sA, long long sB, long long sC)
{
    constexpr uint32_t BSTG   = BT ? BMATB : MATB;
    constexpr uint32_t STAGEB = MATB + BSTG;

    extern __shared__ char smem[];
    const uint32_t sb = smem_u32(smem);
    const int tid = threadIdx.x;
    const int wid = tid >> 5, lane = tid & 31;
    const int wr = wid >> 2, wc = wid & 3;
    const int wm0 = wr * 64, wn0 = wc * 32;

    const int row0 = blockIdx.y << 7, col0 = blockIdx.x << 7;
    const long long zA = (long long)blockIdx.z * sA;
    const long long zB = (long long)blockIdx.z * sB;
    const long long zC = (long long)blockIdx.z * sC;
    const float* biasz = (EPI == 2) ? (bias + blockIdx.z * DD) : bias;

    const __half* gA = Ah + zA + (long long)row0 * K;
    const __half* gB = BT ? (Bh + zB + col0)
                          : (Bh + zB + (long long)col0 * K);

    // A loader: 128 rows x 4x16B units, 2 iters
    const int lrow0 = tid >> 2;
    const int lu    = tid & 3;
    // BT B loader: 32 rows x 16x16B units, 2 iters
    const int btr = tid >> 3;       // 0..31
    const int btu = tid & 7;        // unit base

    float acc[4][4][4];
#pragma unroll
    for (int i = 0; i < 4; i++)
#pragma unroll
        for (int j = 0; j < 4; j++)
#pragma unroll
            for (int q = 0; q < 4; q++) acc[i][j][q] = 0.0f;

    const int NC = K >> 5;

    auto load_chunk = [&](int stage, int kc) {
        const uint32_t sdst = sb + stage * STAGEB;
        // A
        {
            const __half* g = gA + kc * 32;
#pragma unroll
            for (int it = 0; it < 2; it++) {
                const int row = lrow0 + it * 64;
                cpa16(sdst + row * PITCH + lu * 16,
                      g + (long long)row * K + lu * 8);
            }
        }
        // B
        if (BT) {
            const __half* g = gB + (long long)(kc * 32 + btr) * N;
            const uint32_t d = sdst + MATB + btr * BPITCH;
#pragma unroll
            for (int it = 0; it < 2; it++) {
                const int u = btu + it * 8;
                cpa16(d + u * 16, g + u * 8);
            }
        } else {
            const __half* g = gB + kc * 32;
#pragma unroll
            for (int it = 0; it < 2; it++) {
                const int row = lrow0 + it * 64;
                cpa16(sdst + MATB + row * PITCH + lu * 16,
                      g + (long long)row * K + lu * 8);
            }
        }
    };

    load_chunk(0, 0);
    cpa_commit();
    load_chunk(1, 1);
    cpa_commit();

    int s = 0;
    for (int kc = 0; kc < NC; kc++) {
        cpa_wait<1>();
        __syncthreads();

        const uint32_t sAh = sb + s * STAGEB;
        const uint32_t sBh = sAh + MATB;
        const int lr = lane & 15;
        const int lc = (lane >> 4) * 16;

#pragma unroll
        for (int k16 = 0; k16 < 2; k16++) {
            const uint32_t kb = k16 * 32 + lc;
            uint32_t ah[4][4], bh[2][4];
#pragma unroll
            for (int i = 0; i < 4; i++)
                ldm_x4(ah[i], sAh + (uint32_t)(wm0 + i * 16 + lr) * PITCH + kb);
#pragma unroll
            for (int jj = 0; jj < 2; jj++) {
                if (BT)
                    ldm_x4_t(bh[jj], sBh + (uint32_t)(k16 * 16 + lr) * BPITCH
                                        + (uint32_t)(wn0 + jj * 16) * 2 + lc);
                else
                    ldm_x4(bh[jj], sBh + (uint32_t)(wn0 + jj * 16 + lr) * PITCH + kb);
            }
            if (k16 == 0) {
                const int pre = kc + 2;
                if (pre < NC) {
                    int ps = s + 2; if (ps >= 3) ps -= 3;
                    load_chunk(ps, pre);
                }
                cpa_commit();
            }
#pragma unroll
            for (int i = 0; i < 4; i++)
#pragma unroll
                for (int j = 0; j < 4; j++) {
                    const int jj = j >> 1, sel = j & 1;
                    if (BT)
                        mma16816(acc[i][j], ah[i], bh[jj][2*sel], bh[jj][2*sel + 1]);
                    else
                        mma16816(acc[i][j], ah[i], bh[jj][sel], bh[jj][sel + 2]);
                }
        }
        if (++s == 3) s = 0;
    }

    const int er = lane >> 2;
    const int ec = (lane & 3) * 2;
    float esum[4][2];
#pragma unroll
    for (int i = 0; i < 4; i++) { esum[i][0] = 0.0f; esum[i][1] = 0.0f; }

#pragma unroll
    for (int i = 0; i < 4; i++) {
#pragma unroll
        for (int j = 0; j < 4; j++) {
            const int col = col0 + wn0 + j * 8 + ec;
#pragma unroll
            for (int half_m = 0; half_m < 2; half_m++) {
                const int row = row0 + wm0 + i * 16 + er + half_m * 8;
                const float d0 = acc[i][j][half_m * 2 + 0];
                const float d1 = acc[i][j][half_m * 2 + 1];
                if (EPI == 2) {
                    float f0 = d0 + biasz[col];
                    float f1 = d1 + biasz[col + 1];
                    *(__half2*)(Ch + zC + (long long)row * N + col) =
                        __halves2half2(__float2half_rn(f0), __float2half_rn(f1));
                } else if (EPI == 4) {
                    __half h0 = __float2half_rn(ex2(d0 * alpha));
                    __half h1 = __float2half_rn(ex2(d1 * alpha));
                    *(__half2*)(Ch + zC + (long long)row * N + col) = __halves2half2(h0, h1);
                    esum[i][half_m] += __half2float(h0) + __half2float(h1);
                } else {
                    const float inv = 1.0f /
                        rowsum[(long long)blockIdx.z * SS + row];
                    float2 v;
                    v.x = d0 * inv; v.y = d1 * inv;
                    *(float2*)(Cf + zC + (long long)row * N + col) = v;
                }
            }
        }
    }

    if (EPI == 4) {
        __syncthreads();
        float* red = (float*)smem;   // [128][4]
#pragma unroll
        for (int i = 0; i < 4; i++) {
#pragma unroll
            for (int half_m = 0; half_m < 2; half_m++) {
                float v = esum[i][half_m];
                v += __shfl_xor_sync(0xffffffffu, v, 1);
                v += __shfl_xor_sync(0xffffffffu, v, 2);
                if ((lane & 3) == 0)
                    red[(wm0 + i * 16 + half_m * 8 + er) * 4 + wc] = v;
            }
        }
        __syncthreads();
        if (tid < 128) {
            float v = red[tid*4+0] + red[tid*4+1] + red[tid*4+2] + red[tid*4+3];
            atomicAdd(&rowsum[(long long)blockIdx.z * SS + row0 + tid], v);
        }
    }
}

__global__ void __launch_bounds__(256)
cvt_f32_f16(const float* __restrict__ s, __half* __restrict__ h, int n4)
{
    int i = blockIdx.x * 256 + threadIdx.x;
    if (i >= n4) return;
    float4 v = ((const float4*)s)[i];
    *(__half2*)(h + 4*i)     = __halves2half2(__float2half_rn(v.x), __float2half_rn(v.y));
    *(__half2*)(h + 4*i + 2) = __halves2half2(__float2half_rn(v.z), __float2half_rn(v.w));
}

// fp32 [R,C] -> fp16 [C,R]
__global__ void __launch_bounds__(256)
transpose_cvt(const float* __restrict__ src, __half* __restrict__ dst, int R, int C)
{
    __shared__ float t[32][33];
    const int c0 = blockIdx.x * 32, r0 = blockIdx.y * 32;
    const int tx = threadIdx.x, ty = threadIdx.y;
#pragma unroll
    for (int k = 0; k < 4; k++)
        t[ty + 8*k][tx] = src[(long long)(r0 + ty + 8*k) * C + c0 + tx];
    __syncthreads();
#pragma unroll
    for (int k = 0; k < 4; k++)
        dst[(long long)(c0 + ty + 8*k) * R + r0 + tx] = __float2half_rn(t[tx][ty + 8*k]);
}

extern "C" void kernel_launch(void* const* d_in, const int* in_sizes, int n_in,
                              void* d_out, int out_size)
{
    (void)in_sizes; (void)n_in; (void)out_size;
    const float* x  = (const float*)d_in[0];
    const float* Wq = (const float*)d_in[1];
    const float* bq = (const float*)d_in[2];
    const float* Wk = (const float*)d_in[3];
    const float* bk = (const float*)d_in[4];
    const float* Wv = (const float*)d_in[5];
    const float* bv = (const float*)d_in[6];
    float* out = (float*)d_out;

    __half *xh, *Wth, *QKV, *P;
    float *bias, *rowsum;
    cudaGetSymbolAddress((void**)&xh,     g_xh);
    cudaGetSymbolAddress((void**)&Wth,    g_Wth);
    cudaGetSymbolAddress((void**)&bias,   g_bias);
    cudaGetSymbolAddress((void**)&QKV,    g_QKV);
    cudaGetSymbolAddress((void**)&P,      g_P);
    cudaGetSymbolAddress((void**)&rowsum, g_rowsum);

    const int SMEM_NB = 3 * (MATB + MATB);    // 61440 (BT=0)
    const int SMEM_BT = 3 * (MATB + BMATB);   // 56832 (BT=1)
    cudaFuncSetAttribute((const void*)gemm_mma<2,0>, cudaFuncAttributeMaxDynamicSharedMemorySize, SMEM_NB);
    cudaFuncSetAttribute((const void*)gemm_mma<4,0>, cudaFuncAttributeMaxDynamicSharedMemorySize, SMEM_NB);
    cudaFuncSetAttribute((const void*)gemm_mma<5,1>, cudaFuncAttributeMaxDynamicSharedMemorySize, SMEM_BT);

    const float scale = 1.0f / sqrtf((float)DD);
    __half* Qh = QKV + 0 * (long long)MTOT * DD;
    __half* Kh = QKV + 1 * (long long)MTOT * DD;
    __half* Vh = QKV + 2 * (long long)MTOT * DD;

    cudaMemcpyAsync(bias + 0*DD, bq, DD * sizeof(float), cudaMemcpyDeviceToDevice);
    cudaMemcpyAsync(bias + 1*DD, bk, DD * sizeof(float), cudaMemcpyDeviceToDevice);
    cudaMemcpyAsync(bias + 2*DD, bv, DD * sizeof(float), cudaMemcpyDeviceToDevice);

    {
        dim3 tb(32, 8), tg(DD/32, DD/32);
        transpose_cvt<<<tg, tb>>>(Wq, Wth + 0*DD*DD, DD, DD);
        transpose_cvt<<<tg, tb>>>(Wk, Wth + 1*DD*DD, DD, DD);
        transpose_cvt<<<tg, tb>>>(Wv, Wth + 2*DD*DD, DD, DD);
    }
    {
        int n4 = MTOT * DD / 4;
        cvt_f32_f16<<<(n4 + 255) / 256, 256>>>(x, xh, n4);
    }
    // merged Q/K/V projections: z = 0..2
    {
        dim3 g(DD/128, MTOT/128, 3);
        gemm_mma<2,0><<<g, 256, SMEM_NB>>>(xh, Wth, bias, QKV, nullptr, nullptr,
                                           DD, DD, 1.0f,
                                           0, (long long)DD*DD, (long long)MTOT*DD);
    }
    cudaMemsetAsync(rowsum, 0, MTOT * sizeof(float));
    // P = exp(scale * Q K^T), rowsum accumulated
    {
        dim3 g(SS/128, SS/128, BB);
        gemm_mma<4,0><<<g, 256, SMEM_NB>>>(Qh, Kh, nullptr, P, nullptr, rowsum,
                                           SS, DD, scale * L2E,
                                           (long long)SS*DD, (long long)SS*DD,
                                           (long long)SS*SS);
    }
    // out = (P @ V) / rowsum  -- V [seq, emb] used directly via ldmatrix.trans
    {
        dim3 g(DD/128, SS/128, BB);
        gemm_mma<5,1><<<g, 256, SMEM_BT>>>(P, Vh, nullptr, nullptr, out, rowsum,
                                           DD, SS, 1.0f,
                                           (long long)SS*SS, (long long)SS*DD,
                                           (long long)SS*DD);
    }
}